// round 11
// baseline (speedup 1.0000x reference)
#include <cuda_runtime.h>
#include <mma.h>

using namespace nvcuda;

// ----------------------------------------------------------------------------
// NeighborAttention with folded projections + tf32 tensor cores:
//   Wqk[c, h*128+b] = (1/sqrt(32)) * sum_m WQ[32h+m,c] * WK[32h+m,b]   (fp32, tiny)
//   Wvo[h*128+a, c] = sum_j WV[32h+j,a] * WO[c,32h+j]                  (fp32, tiny)
//   Qt  = hV @ Wqk      [N,128]x[128,512]   (tf32 wmma)
//   ctx = masked neighbor attention (persistent fp32 kernel)
//   out = ctx @ Wvo     [N,512]x[512,128]   (tf32 wmma) -> memcpy to d_out
// ----------------------------------------------------------------------------

#define MAXN 30720
#define HDIM 128
#define KNB 32

__device__ float g_Qt[MAXN * 512];
__device__ float g_ctx[MAXN * 512];
__device__ float g_outp[MAXN * 128];
__device__ float g_wqk[128 * 512];
__device__ float g_wvo[512 * 128];

// ----------------------------------------------------------------------------
// Weight folds (fp32). grid = (8, 4): x = 16-wide chunk, y = head.
// ----------------------------------------------------------------------------
__global__ void __launch_bounds__(256) foldqk_kernel(
    const float* __restrict__ WQ, const float* __restrict__ WK, float* __restrict__ Wqk)
{
    __shared__ float WQs[32][16];
    __shared__ alignas(16) float WKs[32][132];
    const int h  = blockIdx.y;
    const int c0 = blockIdx.x * 16;
    const int t  = threadIdx.x;

    for (int i = t; i < 512; i += 256) {
        int m = i >> 4, cc = i & 15;
        WQs[m][cc] = WQ[(32 * h + m) * 128 + c0 + cc];
    }
    #pragma unroll
    for (int i = 0; i < 4; i++) {
        int idx4 = t + 256 * i;
        int m = idx4 >> 5, bc = (idx4 & 31) << 2;
        *(float4*)&WKs[m][bc] = *(const float4*)&WK[(32 * h + m) * 128 + bc];
    }
    __syncthreads();

    const int c  = c0 + (t >> 4);
    const int b0 = (t & 15) << 3;
    float acc[8] = {};
    #pragma unroll
    for (int m = 0; m < 32; m++) {
        float wq = WQs[m][t >> 4];
        float4 k0 = *(const float4*)&WKs[m][b0];
        float4 k1 = *(const float4*)&WKs[m][b0 + 4];
        acc[0] += wq * k0.x; acc[1] += wq * k0.y; acc[2] += wq * k0.z; acc[3] += wq * k0.w;
        acc[4] += wq * k1.x; acc[5] += wq * k1.y; acc[6] += wq * k1.z; acc[7] += wq * k1.w;
    }
    const float scale = 0.17677669529663687f;  // 1/sqrt(32)
    #pragma unroll
    for (int j = 0; j < 8; j++)
        Wqk[c * 512 + h * 128 + b0 + j] = acc[j] * scale;
}

__global__ void __launch_bounds__(256) foldvo_kernel(
    const float* __restrict__ WV, const float* __restrict__ WO, float* __restrict__ Wvo)
{
    __shared__ float WVs[32][16];
    __shared__ alignas(16) float WOsT[32][132];   // WOsT[j][c] = WO[c][32h+j]
    const int h  = blockIdx.y;
    const int a0 = blockIdx.x * 16;
    const int t  = threadIdx.x;

    for (int i = t; i < 512; i += 256) {
        int j = i >> 4, aa = i & 15;
        WVs[j][aa] = WV[(32 * h + j) * 128 + a0 + aa];
    }
    #pragma unroll
    for (int i = 0; i < 4; i++) {
        int idx4 = t + 256 * i;               // 0..1023
        int c = idx4 >> 3, jc = (idx4 & 7) << 2;
        float4 v = *(const float4*)&WO[c * 128 + 32 * h + jc];
        WOsT[jc + 0][c] = v.x;
        WOsT[jc + 1][c] = v.y;
        WOsT[jc + 2][c] = v.z;
        WOsT[jc + 3][c] = v.w;
    }
    __syncthreads();

    const int a  = a0 + (t >> 4);
    const int c0 = (t & 15) << 3;
    float acc[8] = {};
    #pragma unroll
    for (int j = 0; j < 32; j++) {
        float wv = WVs[j][t >> 4];
        float4 o0 = *(const float4*)&WOsT[j][c0];
        float4 o1 = *(const float4*)&WOsT[j][c0 + 4];
        acc[0] += wv * o0.x; acc[1] += wv * o0.y; acc[2] += wv * o0.z; acc[3] += wv * o0.w;
        acc[4] += wv * o1.x; acc[5] += wv * o1.y; acc[6] += wv * o1.z; acc[7] += wv * o1.w;
    }
    #pragma unroll
    for (int j = 0; j < 8; j++)
        Wvo[(h * 128 + a) * 128 + c0 + j] = acc[j];
}

// ----------------------------------------------------------------------------
// tf32 wmma GEMM: C[M,Nc] = A[M,K] @ B[K,Nc], row-major fp32 storage.
// BM=BN=128, BK=32; 256 threads = 8 warps (2x4), warp tile 64x32.
// C must be padded scratch (rows up to gridDim.y*128 are written).
// ----------------------------------------------------------------------------
__global__ void __launch_bounds__(256) tf32_gemm_kernel(
    const float* __restrict__ A, const float* __restrict__ B, float* __restrict__ C,
    int M, int K, int lda, int ldb, int ldc)
{
    __shared__ alignas(16) float As[128][40];
    __shared__ alignas(16) float Bs[32][136];

    const int t    = threadIdx.x;
    const int m0   = blockIdx.y * 128;
    const int n0   = blockIdx.x * 128;
    const int warp = t >> 5;
    const int wr   = warp >> 2;   // 0..1
    const int wc   = warp & 3;    // 0..3

    wmma::fragment<wmma::accumulator, 16, 16, 8, float> cf[4][2];
    #pragma unroll
    for (int i = 0; i < 4; i++)
        #pragma unroll
        for (int j = 0; j < 2; j++)
            wmma::fill_fragment(cf[i][j], 0.f);

    for (int k0 = 0; k0 < K; k0 += 32) {
        // A tile 128x32
        #pragma unroll
        for (int i = 0; i < 4; i++) {
            int idx4 = t + 256 * i;            // 0..1023
            int r = idx4 >> 3, kc = (idx4 & 7) << 2;
            float4 v = make_float4(0.f, 0.f, 0.f, 0.f);
            if (m0 + r < M) v = *(const float4*)&A[(long long)(m0 + r) * lda + k0 + kc];
            *(float4*)&As[r][kc] = v;
        }
        // B tile 32x128
        #pragma unroll
        for (int i = 0; i < 4; i++) {
            int idx4 = t + 256 * i;
            int kr = idx4 >> 5, nc = (idx4 & 31) << 2;
            *(float4*)&Bs[kr][nc] = *(const float4*)&B[(long long)(k0 + kr) * ldb + n0 + nc];
        }
        __syncthreads();

        #pragma unroll
        for (int ks = 0; ks < 32; ks += 8) {
            wmma::fragment<wmma::matrix_a, 16, 16, 8, wmma::precision::tf32, wmma::row_major> af[4];
            wmma::fragment<wmma::matrix_b, 16, 16, 8, wmma::precision::tf32, wmma::row_major> bf[2];
            #pragma unroll
            for (int i = 0; i < 4; i++) {
                wmma::load_matrix_sync(af[i], &As[wr * 64 + 16 * i][ks], 40);
                #pragma unroll
                for (int e = 0; e < af[i].num_elements; e++)
                    af[i].x[e] = wmma::__float_to_tf32(af[i].x[e]);
            }
            #pragma unroll
            for (int j = 0; j < 2; j++) {
                wmma::load_matrix_sync(bf[j], &Bs[ks][wc * 32 + 16 * j], 136);
                #pragma unroll
                for (int e = 0; e < bf[j].num_elements; e++)
                    bf[j].x[e] = wmma::__float_to_tf32(bf[j].x[e]);
            }
            #pragma unroll
            for (int i = 0; i < 4; i++)
                #pragma unroll
                for (int j = 0; j < 2; j++)
                    wmma::mma_sync(cf[i][j], af[i], bf[j], cf[i][j]);
        }
        __syncthreads();
    }

    #pragma unroll
    for (int i = 0; i < 4; i++)
        #pragma unroll
        for (int j = 0; j < 2; j++)
            wmma::store_matrix_sync(
                &C[(long long)(m0 + wr * 64 + 16 * i) * ldc + n0 + wc * 32 + 16 * j],
                cf[i][j], ldc, wmma::mem_row_major);
}

// ----------------------------------------------------------------------------
// Persistent fused neighbor attention (unchanged from R10 win).
// ----------------------------------------------------------------------------
__global__ void __launch_bounds__(128) attn_kernel(
    const float* __restrict__ hE, const int* __restrict__ mask,
    const float* __restrict__ Qt, float* __restrict__ ctx, int N)
{
    __shared__ float Es[32 * 132];
    __shared__ float Qts[4 * 132];
    __shared__ float Lp[512];
    __shared__ float Asm[128];
    __shared__ int   msk[3][32];

    const int t  = threadIdx.x;
    const int G  = gridDim.x;
    const int n0 = blockIdx.x;
    if (n0 >= N) return;

    if (t < 32) {
        msk[0][t] = mask[(long long)n0 * KNB + t];
        long long n1 = n0 + (long long)G;
        msk[1][t] = (n1 < N) ? mask[n1 * KNB + t] : 0;
    }
    __syncthreads();

    float4 ereg[8];
    float4 qreg;

    {
        const float* e = hE + (long long)n0 * (KNB * HDIM);
        #pragma unroll
        for (int ii = 0; ii < 8; ii++) {
            int idx4 = t + 128 * ii;
            int k = idx4 >> 5;
            ereg[ii] = make_float4(0.f, 0.f, 0.f, 0.f);
            if (msk[0][k]) ereg[ii] = *(const float4*)&e[idx4 << 2];
        }
        qreg = *(const float4*)&Qt[(long long)n0 * 512 + t * 4];
        #pragma unroll
        for (int ii = 0; ii < 8; ii++) {
            int idx4 = t + 128 * ii;
            int k = idx4 >> 5, a4 = idx4 & 31;
            *(float4*)&Es[k * 132 + (a4 << 2)] = ereg[ii];
        }
        int h = t >> 5, a4 = t & 31;
        *(float4*)&Qts[h * 132 + (a4 << 2)] = qreg;
    }
    __syncthreads();

    for (int i = 0; ; i++) {
        const long long n  = n0 + (long long)i * G;
        const long long nn = n + G;
        const bool has_next = (nn < N);
        int mreg = 0;

        if (has_next) {
            const int s1 = (i + 1) % 3;
            const float* e = hE + nn * (KNB * HDIM);
            #pragma unroll
            for (int ii = 0; ii < 8; ii++) {
                int idx4 = t + 128 * ii;
                int k = idx4 >> 5;
                ereg[ii] = make_float4(0.f, 0.f, 0.f, 0.f);
                if (msk[s1][k]) ereg[ii] = *(const float4*)&e[idx4 << 2];
            }
            qreg = *(const float4*)&Qt[nn * 512 + t * 4];
            if (t < 32) {
                long long n2 = n + 2LL * G;
                mreg = (n2 < N) ? mask[n2 * KNB + t] : 0;
            }
        }

        const int* mc = msk[i % 3];

        {
            const int ac = t >> 5;
            const int k  = t & 31;
            const float* ep = &Es[k * 132 + (ac << 5)];
            float p0 = 0.f, p1 = 0.f, p2 = 0.f, p3 = 0.f;
            #pragma unroll
            for (int s = 0; s < 8; s++) {
                float4 e4 = *(const float4*)&ep[s << 2];
                int ao = (ac << 5) + (s << 2);
                float4 q0 = *(const float4*)&Qts[0 * 132 + ao];
                float4 q1 = *(const float4*)&Qts[1 * 132 + ao];
                float4 q2 = *(const float4*)&Qts[2 * 132 + ao];
                float4 q3 = *(const float4*)&Qts[3 * 132 + ao];
                p0 += q0.x * e4.x + q0.y * e4.y + q0.z * e4.z + q0.w * e4.w;
                p1 += q1.x * e4.x + q1.y * e4.y + q1.z * e4.z + q1.w * e4.w;
                p2 += q2.x * e4.x + q2.y * e4.y + q2.z * e4.z + q2.w * e4.w;
                p3 += q3.x * e4.x + q3.y * e4.y + q3.z * e4.z + q3.w * e4.w;
            }
            Lp[(ac << 7) + 0 * 32 + k] = p0;
            Lp[(ac << 7) + 1 * 32 + k] = p1;
            Lp[(ac << 7) + 2 * 32 + k] = p2;
            Lp[(ac << 7) + 3 * 32 + k] = p3;
        }
        __syncthreads();

        {
            const int h = t >> 5, k = t & 31;
            float x = Lp[0 * 128 + h * 32 + k] + Lp[1 * 128 + h * 32 + k]
                    + Lp[2 * 128 + h * 32 + k] + Lp[3 * 128 + h * 32 + k];
            bool mv  = (mc[k] != 0);
            float xm = mv ? x : -3.402823466e+38f;
            float mx = xm;
            #pragma unroll
            for (int o = 16; o > 0; o >>= 1) mx = fmaxf(mx, __shfl_xor_sync(0xffffffffu, mx, o));
            float p = mv ? __expf(xm - mx) : 0.f;
            float sm = p;
            #pragma unroll
            for (int o = 16; o > 0; o >>= 1) sm += __shfl_xor_sync(0xffffffffu, sm, o);
            float inv = (sm > 0.f) ? (1.f / sm) : 0.f;
            Asm[h * 32 + k] = p * inv;
        }
        __syncthreads();

        {
            float c0 = 0.f, c1 = 0.f, c2 = 0.f, c3 = 0.f;
            #pragma unroll
            for (int k4 = 0; k4 < 8; k4++) {
                float4 a0 = *(const float4*)&Asm[0 * 32 + (k4 << 2)];
                float4 a1 = *(const float4*)&Asm[1 * 32 + (k4 << 2)];
                float4 a2 = *(const float4*)&Asm[2 * 32 + (k4 << 2)];
                float4 a3 = *(const float4*)&Asm[3 * 32 + (k4 << 2)];
                float w0[4] = {a0.x, a0.y, a0.z, a0.w};
                float w1[4] = {a1.x, a1.y, a1.z, a1.w};
                float w2[4] = {a2.x, a2.y, a2.z, a2.w};
                float w3[4] = {a3.x, a3.y, a3.z, a3.w};
                #pragma unroll
                for (int ii = 0; ii < 4; ii++) {
                    float ev = Es[((k4 << 2) + ii) * 132 + t];
                    c0 += w0[ii] * ev;
                    c1 += w1[ii] * ev;
                    c2 += w2[ii] * ev;
                    c3 += w3[ii] * ev;
                }
            }
            float* cp = ctx + n * 512 + t;
            cp[0]   = c0;
            cp[128] = c1;
            cp[256] = c2;
            cp[384] = c3;
        }

        if (!has_next) break;

        __syncthreads();
        #pragma unroll
        for (int ii = 0; ii < 8; ii++) {
            int idx4 = t + 128 * ii;
            int k = idx4 >> 5, a4 = idx4 & 31;
            *(float4*)&Es[k * 132 + (a4 << 2)] = ereg[ii];
        }
        {
            int h = t >> 5, a4 = t & 31;
            *(float4*)&Qts[h * 132 + (a4 << 2)] = qreg;
        }
        if (t < 32) msk[(i + 2) % 3][t] = mreg;
        __syncthreads();
    }
}

// ----------------------------------------------------------------------------
extern "C" void kernel_launch(void* const* d_in, const int* in_sizes, int n_in,
                              void* d_out, int out_size)
{
    const float* hV   = (const float*)d_in[0];
    const float* hE   = (const float*)d_in[1];
    const int*   mask = (const int*)  d_in[2];
    const float* WQ   = (const float*)d_in[3];
    const float* WK   = (const float*)d_in[4];
    const float* WV   = (const float*)d_in[5];
    const float* WO   = (const float*)d_in[6];
    float*       out  = (float*)d_out;

    const int N = in_sizes[0] / HDIM;
    if (N <= 0) return;

    float *Qt, *Ctx, *Outp, *Wqk, *Wvo;
    cudaGetSymbolAddress((void**)&Qt,   g_Qt);
    cudaGetSymbolAddress((void**)&Ctx,  g_ctx);
    cudaGetSymbolAddress((void**)&Outp, g_outp);
    cudaGetSymbolAddress((void**)&Wqk,  g_wqk);
    cudaGetSymbolAddress((void**)&Wvo,  g_wvo);

    const int MB128 = (N + 127) / 128;

    // 1) fold weights (fp32, tiny)
    foldqk_kernel<<<dim3(8, 4), 256>>>(WQ, WK, Wqk);
    foldvo_kernel<<<dim3(8, 4), 256>>>(WV, WO, Wvo);

    // 2) Qt = hV @ Wqk   [N,128]x[128,512]  (tf32)
    tf32_gemm_kernel<<<dim3(4, MB128), 256>>>(hV, Wqk, Qt, N, 128, 128, 512, 512);

    // 3) persistent fused attention -> ctx[N,512]
    int attn_grid = 888;
    if (attn_grid > N) attn_grid = N;
    attn_kernel<<<attn_grid, 128>>>(hE, mask, Qt, Ctx, N);

    // 4) out = ctx @ Wvo  [N,512]x[512,128]  (tf32) -> padded scratch
    tf32_gemm_kernel<<<dim3(1, MB128), 256>>>(Ctx, Wvo, Outp, N, 512, 512, 128, 128);

    // 5) copy exact-size result
    cudaMemcpyAsync(out, Outp, (size_t)N * 128 * sizeof(float),
                    cudaMemcpyDeviceToDevice);
}

// round 12
// speedup vs baseline: 1.2533x; 1.2533x over previous
#include <cuda_runtime.h>

// ----------------------------------------------------------------------------
// NeighborAttention (63 GFLOP -> 3.9 GFLOP), 5 launches:
//   1) Q   = hV @ WQ^T
//   2) Qt  = (1/sqrt(32)) * Q_h @ WK_h
//   3) attn: persistent, pipelined, fully mask-predicated  -> ctx
//   4) vout = ctx_h @ WV_h^T
//   5) out  = vout @ WO^T
// Masked neighbor rows are never loaded, stored, or computed; stale smem in
// those rows is safe because their softmax weight is exactly zero and all
// consumers are predicated.
// ----------------------------------------------------------------------------

#define MAXN 30720
#define HDIM 128
#define KNB 32

__device__ float g_Q[MAXN * 128];
__device__ float g_Qt[MAXN * 512];
__device__ float g_ctx[MAXN * 512];
__device__ float g_vout[MAXN * 128];

// ----------------------------------------------------------------------------
// Tiled SGEMM, 8x8 / 8x4 register microtiles (R10-proven).
// ----------------------------------------------------------------------------
template <int BM, int BN, int BK, int TM, int TN, bool TRANSB>
__global__ void __launch_bounds__((BM / TM) * (BN / TN)) sgemm_kernel(
    const float* __restrict__ A, const float* __restrict__ B, float* __restrict__ C,
    int M, int Nc, int K, int lda, int ldb, int ldc,
    long long aB, long long bB, long long cB, float alpha)
{
    constexpr int NT = (BM / TM) * (BN / TN);
    __shared__ float As[BK][BM + 4];
    __shared__ float Bs[BK][BN + 4];

    const long long bz = blockIdx.z;
    A += bz * aB; B += bz * bB; C += bz * cB;

    const int m0 = blockIdx.y * BM;
    const int n0 = blockIdx.x * BN;
    const int t  = threadIdx.x;
    const int tm = t / (BN / TN);
    const int tn = t % (BN / TN);

    float acc[TM][TN] = {};

    for (int k0 = 0; k0 < K; k0 += BK) {
        constexpr int A4 = (BM * BK) / (4 * NT);
        #pragma unroll
        for (int i = 0; i < A4; i++) {
            int idx4 = t + NT * i;
            int r  = idx4 / (BK / 4);
            int kc = (idx4 % (BK / 4)) * 4;
            float4 v = make_float4(0.f, 0.f, 0.f, 0.f);
            int gr = m0 + r;
            if (gr < M) v = *(const float4*)&A[(long long)gr * lda + k0 + kc];
            As[kc + 0][r] = v.x;
            As[kc + 1][r] = v.y;
            As[kc + 2][r] = v.z;
            As[kc + 3][r] = v.w;
        }
        if (!TRANSB) {
            constexpr int B4 = (BK * BN) / (4 * NT);
            #pragma unroll
            for (int i = 0; i < B4; i++) {
                int idx4 = t + NT * i;
                int kr = idx4 / (BN / 4);
                int nc = (idx4 % (BN / 4)) * 4;
                float4 v = make_float4(0.f, 0.f, 0.f, 0.f);
                if (n0 + nc < Nc) v = *(const float4*)&B[(long long)(k0 + kr) * ldb + n0 + nc];
                *(float4*)&Bs[kr][nc] = v;
            }
        } else {
            constexpr int B4 = (BN * BK) / (4 * NT);
            #pragma unroll
            for (int i = 0; i < B4; i++) {
                int idx4 = t + NT * i;
                int n  = idx4 / (BK / 4);
                int kc = (idx4 % (BK / 4)) * 4;
                float4 v = make_float4(0.f, 0.f, 0.f, 0.f);
                if (n0 + n < Nc) v = *(const float4*)&B[(long long)(n0 + n) * ldb + k0 + kc];
                Bs[kc + 0][n] = v.x;
                Bs[kc + 1][n] = v.y;
                Bs[kc + 2][n] = v.z;
                Bs[kc + 3][n] = v.w;
            }
        }
        __syncthreads();

        #pragma unroll
        for (int kk = 0; kk < BK; kk++) {
            float a[TM], b[TN];
            #pragma unroll
            for (int h = 0; h < TM / 4; h++) {
                float4 v = *(const float4*)&As[kk][tm * 4 + h * (BM / 2)];
                a[h * 4 + 0] = v.x; a[h * 4 + 1] = v.y;
                a[h * 4 + 2] = v.z; a[h * 4 + 3] = v.w;
            }
            #pragma unroll
            for (int h = 0; h < TN / 4; h++) {
                float4 v = *(const float4*)&Bs[kk][tn * 4 + h * (BN / 2)];
                b[h * 4 + 0] = v.x; b[h * 4 + 1] = v.y;
                b[h * 4 + 2] = v.z; b[h * 4 + 3] = v.w;
            }
            #pragma unroll
            for (int i = 0; i < TM; i++)
                #pragma unroll
                for (int j = 0; j < TN; j++)
                    acc[i][j] += a[i] * b[j];
        }
        __syncthreads();
    }

    #pragma unroll
    for (int i = 0; i < TM; i++) {
        int r = m0 + tm * 4 + (i / 4) * (BM / 2) + (i % 4);
        if (r >= M) continue;
        #pragma unroll
        for (int jh = 0; jh < TN / 4; jh++) {
            int c = n0 + tn * 4 + jh * (BN / 2);
            if (c < Nc) {
                float4 v = make_float4(acc[i][jh * 4 + 0] * alpha, acc[i][jh * 4 + 1] * alpha,
                                       acc[i][jh * 4 + 2] * alpha, acc[i][jh * 4 + 3] * alpha);
                *(float4*)&C[(long long)r * ldc + c] = v;
            }
        }
    }
}

// ----------------------------------------------------------------------------
// Persistent fused neighbor attention, fully mask-predicated.
// ----------------------------------------------------------------------------
__global__ void __launch_bounds__(128) attn_kernel(
    const float* __restrict__ hE, const int* __restrict__ mask,
    const float* __restrict__ Qt, float* __restrict__ ctx, int N)
{
    __shared__ float Es[32 * 132];
    __shared__ float Qts[4 * 132];
    __shared__ float Lp[512];
    __shared__ float Asm[128];
    __shared__ int   msk[3][32];

    const int t  = threadIdx.x;
    const int G  = gridDim.x;
    const int n0 = blockIdx.x;
    if (n0 >= N) return;

    if (t < 32) {
        msk[0][t] = mask[(long long)n0 * KNB + t];
        long long n1 = n0 + (long long)G;
        msk[1][t] = (n1 < N) ? mask[n1 * KNB + t] : 0;
    }
    __syncthreads();

    float4 ereg[8];
    float4 qreg;

    // --- prologue: load + commit node n0 (masked rows skipped entirely) ---
    {
        const float* e = hE + (long long)n0 * (KNB * HDIM);
        #pragma unroll
        for (int ii = 0; ii < 8; ii++) {
            int idx4 = t + 128 * ii;
            int k = idx4 >> 5;                       // warp-uniform
            if (msk[0][k]) {
                ereg[ii] = *(const float4*)&e[idx4 << 2];
                int a4 = idx4 & 31;
                *(float4*)&Es[k * 132 + (a4 << 2)] = ereg[ii];
            }
        }
        qreg = *(const float4*)&Qt[(long long)n0 * 512 + t * 4];
        int h = t >> 5, a4 = t & 31;
        *(float4*)&Qts[h * 132 + (a4 << 2)] = qreg;
    }
    __syncthreads();

    for (int i = 0; ; i++) {
        const long long n  = n0 + (long long)i * G;
        const long long nn = n + G;
        const bool has_next = (nn < N);
        int mreg = 0;

        // --- phase A: prefetch node nn into registers (masked rows skipped) ---
        if (has_next) {
            const int s1 = (i + 1) % 3;
            const float* e = hE + nn * (KNB * HDIM);
            #pragma unroll
            for (int ii = 0; ii < 8; ii++) {
                int idx4 = t + 128 * ii;
                int k = idx4 >> 5;                   // warp-uniform
                if (msk[s1][k]) ereg[ii] = *(const float4*)&e[idx4 << 2];
            }
            qreg = *(const float4*)&Qt[nn * 512 + t * 4];
            if (t < 32) {
                long long n2 = n + 2LL * G;
                mreg = (n2 < N) ? mask[n2 * KNB + t] : 0;
            }
        }

        // --- phase B: compute node n from smem ---
        const int* mc = msk[i % 3];

        {   // logits partials: warp = a-chunk, lane = k; masked lanes idle
            const int ac = t >> 5;
            const int k  = t & 31;
            float p0 = 0.f, p1 = 0.f, p2 = 0.f, p3 = 0.f;
            if (mc[k]) {
                const float* ep = &Es[k * 132 + (ac << 5)];
                #pragma unroll
                for (int s = 0; s < 8; s++) {
                    float4 e4 = *(const float4*)&ep[s << 2];
                    int ao = (ac << 5) + (s << 2);
                    float4 q0 = *(const float4*)&Qts[0 * 132 + ao];   // broadcast
                    float4 q1 = *(const float4*)&Qts[1 * 132 + ao];
                    float4 q2 = *(const float4*)&Qts[2 * 132 + ao];
                    float4 q3 = *(const float4*)&Qts[3 * 132 + ao];
                    p0 += q0.x * e4.x + q0.y * e4.y + q0.z * e4.z + q0.w * e4.w;
                    p1 += q1.x * e4.x + q1.y * e4.y + q1.z * e4.z + q1.w * e4.w;
                    p2 += q2.x * e4.x + q2.y * e4.y + q2.z * e4.z + q2.w * e4.w;
                    p3 += q3.x * e4.x + q3.y * e4.y + q3.z * e4.z + q3.w * e4.w;
                }
            }
            Lp[(ac << 7) + 0 * 32 + k] = p0;
            Lp[(ac << 7) + 1 * 32 + k] = p1;
            Lp[(ac << 7) + 2 * 32 + k] = p2;
            Lp[(ac << 7) + 3 * 32 + k] = p3;
        }
        __syncthreads();

        {   // masked softmax: warp = head, lane = k
            const int h = t >> 5, k = t & 31;
            float x = Lp[0 * 128 + h * 32 + k] + Lp[1 * 128 + h * 32 + k]
                    + Lp[2 * 128 + h * 32 + k] + Lp[3 * 128 + h * 32 + k];
            bool mv  = (mc[k] != 0);
            float xm = mv ? x : -3.402823466e+38f;
            float mx = xm;
            #pragma unroll
            for (int o = 16; o > 0; o >>= 1) mx = fmaxf(mx, __shfl_xor_sync(0xffffffffu, mx, o));
            float p = mv ? __expf(xm - mx) : 0.f;
            float sm = p;
            #pragma unroll
            for (int o = 16; o > 0; o >>= 1) sm += __shfl_xor_sync(0xffffffffu, sm, o);
            float inv = (sm > 0.f) ? (1.f / sm) : 0.f;
            Asm[h * 32 + k] = p * inv;
        }
        __syncthreads();

        {   // ctx: thread t owns column a = t; masked rows skipped (w == 0)
            float c0 = 0.f, c1 = 0.f, c2 = 0.f, c3 = 0.f;
            #pragma unroll
            for (int k4 = 0; k4 < 8; k4++) {
                float4 a0 = *(const float4*)&Asm[0 * 32 + (k4 << 2)];
                float4 a1 = *(const float4*)&Asm[1 * 32 + (k4 << 2)];
                float4 a2 = *(const float4*)&Asm[2 * 32 + (k4 << 2)];
                float4 a3 = *(const float4*)&Asm[3 * 32 + (k4 << 2)];
                float w0[4] = {a0.x, a0.y, a0.z, a0.w};
                float w1[4] = {a1.x, a1.y, a1.z, a1.w};
                float w2[4] = {a2.x, a2.y, a2.z, a2.w};
                float w3[4] = {a3.x, a3.y, a3.z, a3.w};
                #pragma unroll
                for (int ii = 0; ii < 4; ii++) {
                    int row = (k4 << 2) + ii;
                    if (mc[row]) {                       // warp-uniform skip
                        float ev = Es[row * 132 + t];
                        c0 += w0[ii] * ev;
                        c1 += w1[ii] * ev;
                        c2 += w2[ii] * ev;
                        c3 += w3[ii] * ev;
                    }
                }
            }
            float* cp = ctx + n * 512 + t;
            cp[0]   = c0;
            cp[128] = c1;
            cp[256] = c2;
            cp[384] = c3;
        }

        if (!has_next) break;

        // --- phase C: commit prefetched tile (masked rows skipped) ---
        __syncthreads();
        {
            const int s1 = (i + 1) % 3;
            #pragma unroll
            for (int ii = 0; ii < 8; ii++) {
                int idx4 = t + 128 * ii;
                int k = idx4 >> 5;                   // warp-uniform
                if (msk[s1][k]) {
                    int a4 = idx4 & 31;
                    *(float4*)&Es[k * 132 + (a4 << 2)] = ereg[ii];
                }
            }
            int h = t >> 5, a4 = t & 31;
            *(float4*)&Qts[h * 132 + (a4 << 2)] = qreg;
        }
        if (t < 32) msk[(i + 2) % 3][t] = mreg;
        __syncthreads();
    }
}

// ----------------------------------------------------------------------------
extern "C" void kernel_launch(void* const* d_in, const int* in_sizes, int n_in,
                              void* d_out, int out_size)
{
    const float* hV   = (const float*)d_in[0];
    const float* hE   = (const float*)d_in[1];
    const int*   mask = (const int*)  d_in[2];
    const float* WQ   = (const float*)d_in[3];
    const float* WK   = (const float*)d_in[4];
    const float* WV   = (const float*)d_in[5];
    const float* WO   = (const float*)d_in[6];
    float*       out  = (float*)d_out;

    const int N = in_sizes[0] / HDIM;
    if (N <= 0) return;

    float *Q, *Qt, *Ctx, *Vout;
    cudaGetSymbolAddress((void**)&Q,    g_Q);
    cudaGetSymbolAddress((void**)&Qt,   g_Qt);
    cudaGetSymbolAddress((void**)&Ctx,  g_ctx);
    cudaGetSymbolAddress((void**)&Vout, g_vout);

    const int MB64  = (N + 63) / 64;
    const int MB128 = (N + 127) / 128;
    const float inv_sqrt_d = 0.17677669529663687f;  // 1/sqrt(32)

    // 1) Q = h_V @ W_Q^T
    sgemm_kernel<64, 128, 16, 8, 8, true><<<dim3(1, MB64, 1), 128>>>(
        hV, WQ, Q, N, 128, 128, 128, 128, 128, 0, 0, 0, 1.f);

    // 2) Qt[n, h*128+b] = (1/sqrt(d)) * Q[n,32h:32h+32] @ W_K[32h:32h+32,:]
    sgemm_kernel<64, 128, 16, 8, 8, false><<<dim3(1, MB64, 4), 128>>>(
        Q, WK, Qt, N, 128, 32, 128, 128, 512,
        /*aB=*/32, /*bB=*/32 * 128, /*cB=*/128, inv_sqrt_d);

    // 3) persistent fused attention -> ctx[N,512]  (9 CTAs/SM)
    int attn_grid = 1332;
    if (attn_grid > N) attn_grid = N;
    attn_kernel<<<attn_grid, 128>>>(hE, mask, Qt, Ctx, N);

    // 4) vout[n, 32h+j] = ctx[n, 128h:] @ W_V[32h+j,:]
    sgemm_kernel<128, 32, 16, 8, 4, true><<<dim3(1, MB128, 4), 128>>>(
        Ctx, WV, Vout, N, 32, 128, 512, 128, 128,
        /*aB=*/128, /*bB=*/32 * 128, /*cB=*/32, 1.f);

    // 5) out = vout @ W_O^T
    sgemm_kernel<64, 128, 16, 8, 8, true><<<dim3(1, MB64, 1), 128>>>(
        Vout, WO, out, N, 128, 128, 128, 128, 128, 0, 0, 0, 1.f);
}